// round 12
// baseline (speedup 1.0000x reference)
#include <cuda_runtime.h>
#include <cuda_bf16.h>

// A = 8160 (68x120,s=8) + 2040 (34x60,s=16) + 510 (17x30,s=32) = 10710
// Output: [decoded B*A*16][fg B*A][ibc B*G*A], all f32.
//
// Separable masks: in_box(a,g) = xtest(col) & ytest(row). 50-bit tables per
// column/row; per anchor = 64-bit ANDs. Mask blocks stage per-anchor "both"
// bitmasks in shared (plus a 2-shifted shadow so odd-g rows can use aligned
// 128-bit ld/st), then expand 50 g-rows x 128 quads as a flat task loop.

#define A_TOTAL 10710
#define A_L0    8160
#define A_L01   10200
#define NB      32
#define NG      50
#define NCH     16

#define NCOLS   210
#define NROWS   119

#define MASK_PER_BLK 512
#define MASK_ABLKS   ((A_TOTAL + MASK_PER_BLK - 1) / MASK_PER_BLK)  // 21
#define MASK_BLOCKS  (MASK_ABLKS * NB)        // 672
#define TOTF4        (NB * A_TOTAL * 4)       // 1370880
#define COPY_BLOCKS  ((TOTF4 + 1023) / 1024)  // 1339 (4 float4 per thread)

__device__ __forceinline__ float bit2f(unsigned int word, int g) {
    // ((word >> g) & 1) ? 1.0f : 0.0f  via sign-extend trick (3 ALU ops)
    const unsigned int m = (unsigned int)(((int)(word << (31 - g))) >> 31);
    return __uint_as_float(m & 0x3f800000u);
}

__device__ __forceinline__ void anchor_geom(int a, int& L, int& row, int& col) {
    int i, w;
    if (a < A_L0)       { L = 0; i = a;          w = 120; }
    else if (a < A_L01) { L = 1; i = a - A_L0;   w = 60;  }
    else                { L = 2; i = a - A_L01;  w = 30;  }
    row = i / w;
    col = i - row * w;
}

// global row index 0..118 (monotone in a)
__device__ __forceinline__ int grow_of(int a) {
    if (a < A_L0)   return a / 120;
    if (a < A_L01)  return 68 + (a - A_L0) / 60;
    return 102 + (a - A_L01) / 30;
}

__global__ __launch_bounds__(256)
void main_kernel(const float* __restrict__ preds,
                 const float* __restrict__ labels,
                 float* __restrict__ out) {
    __shared__ float4 sbox[NG];
    __shared__ float4 sctr[3][NG];
    __shared__ ulonglong2 sx[NCOLS];             // .x = box bits, .y = ctr bits
    __shared__ ulonglong2 sy[NROWS];
    __shared__ unsigned int slo[MASK_PER_BLK];   // both bits [0,32)
    __shared__ unsigned int shi[MASK_PER_BLK];   // both bits [32,50)
    __shared__ unsigned int slo2[MASK_PER_BLK];  // slo shifted by 2 (odd-g path)
    __shared__ unsigned int shi2[MASK_PER_BLK];

    const int blk = blockIdx.x;
    const int tid = threadIdx.x;

    if (blk >= MASK_BLOCKS) {
        // ============ copy/decode role: 4 float4/thread, hoisted loads ======
        const int cb = blk - MASK_BLOCKS;
        const float4* __restrict__ p4 = reinterpret_cast<const float4*>(preds);
        float4* __restrict__ o4 = reinterpret_cast<float4*>(out);

        const int j0 = cb * 1024 + tid;
        float4 v[4];
#pragma unroll
        for (int it = 0; it < 4; ++it) {
            const int j = j0 + it * 256;
            if (j < TOTF4) v[it] = p4[j];
        }
#pragma unroll
        for (int it = 0; it < 4; ++it) {
            const int j = j0 + it * 256;
            if (j >= TOTF4) break;
            float4 w = v[it];
            if ((j & 3) == 0) {                  // channels 0..3 of some anchor
                const int alin = j >> 2;
                const int b = alin / A_TOTAL;
                const int a = alin - b * A_TOTAL;
                int L, row, col;
                anchor_geom(a, L, row, col);
                const float s = (L == 0) ? 8.0f : (L == 1) ? 16.0f : 32.0f;
                float4 r;
                r.x = (w.x + (float)col) * s;
                r.y = (w.y + (float)row) * s;
                r.z = __expf(w.z) * s;
                r.w = __expf(w.w) * s;
                w = r;
            }
            o4[j] = w;
        }
        return;
    }

    // ======================= mask role ======================================
    const int b     = blk / MASK_ABLKS;
    const int abase = (blk % MASK_ABLKS) * MASK_PER_BLK;
    const int nA    = min(MASK_PER_BLK, A_TOTAL - abase);
    const int alast = abase + nA - 1;

    const float PINF = __int_as_float(0x7f800000);
    const float NINF = __int_as_float(0xff800000);

    // Phase 1: label bounds into shared
    if (tid < 3 * NG) {
        const int L = tid / NG;
        const int g = tid % NG;
        const float* lb = labels + ((size_t)b * NG + g) * 5;
        const float c  = lb[0];
        const float gx = lb[1];
        const float gy = lb[2];
        const float gw = lb[3];
        const float gh = lb[4];
        const bool valid = (c + gx + gy + gw + gh) > 0.0f;  // invalid rows are exactly 0
        if (L == 0) {
            const float hw = 0.5f * gw, hh = 0.5f * gh;
            sbox[g] = valid ? make_float4(gx - hw, gx + hw, gy - hh, gy + hh)
                            : make_float4(PINF, NINF, PINF, NINF);
        }
        const float r = (L == 0) ? 20.0f : (L == 1) ? 40.0f : 80.0f;  // 2.5*stride
        sctr[L][g] = valid ? make_float4(gx - r, gx + r, gy - r, gy + r)
                           : make_float4(PINF, NINF, PINF, NINF);
    }
    __syncthreads();

    // Phase 2: build ONLY the table entries this block touches (<=193, 1 pass)
    {
        const int Llo = (abase < A_L0) ? 0 : (abase < A_L01) ? 1 : 2;
        const int Lhi = (alast < A_L0) ? 0 : (alast < A_L01) ? 1 : 2;
        const int col_lo = (Llo == 0) ? 0 : (Llo == 1) ? 120 : 180;
        const int col_hi = (Lhi == 0) ? 119 : (Lhi == 1) ? 179 : 209;
        const int row_lo = grow_of(abase);
        const int row_hi = grow_of(alast);
        const int ncols = col_hi - col_lo + 1;
        const int nrows = row_hi - row_lo + 1;     // ncols + nrows <= 193 < 256

        if (tid < ncols) {
            const int gc = col_lo + tid;
            int L, col; float s;
            if (gc < 120)      { L = 0; col = gc;        s = 8.0f;  }
            else if (gc < 180) { L = 1; col = gc - 120;  s = 16.0f; }
            else               { L = 2; col = gc - 180;  s = 32.0f; }
            const float xc = ((float)col + 0.5f) * s;
            unsigned long long bb = 0ull, cc = 0ull;
#pragma unroll
            for (int g = 0; g < NG; ++g) {
                const float4 B = sbox[g];
                const float4 C = sctr[L][g];
                if (fminf(xc - B.x, B.y - xc) > 0.0f) bb |= (1ull << g);
                if (fminf(xc - C.x, C.y - xc) > 0.0f) cc |= (1ull << g);
            }
            sx[gc] = make_ulonglong2(bb, cc);
        } else if (tid < ncols + nrows) {
            const int gr = row_lo + (tid - ncols);
            int L, row; float s;
            if (gr < 68)       { L = 0; row = gr;       s = 8.0f;  }
            else if (gr < 102) { L = 1; row = gr - 68;  s = 16.0f; }
            else               { L = 2; row = gr - 102; s = 32.0f; }
            const float yc = ((float)row + 0.5f) * s;
            unsigned long long bb = 0ull, cc = 0ull;
#pragma unroll
            for (int g = 0; g < NG; ++g) {
                const float4 B = sbox[g];
                const float4 C = sctr[L][g];
                if (fminf(yc - B.z, B.w - yc) > 0.0f) bb |= (1ull << g);
                if (fminf(yc - C.z, C.w - yc) > 0.0f) cc |= (1ull << g);
            }
            sy[gr] = make_ulonglong2(bb, cc);
        }
    }
    __syncthreads();

    float* out_fg  = out + (size_t)NB * A_TOTAL * NCH;
    float* out_ibc = out_fg + (size_t)NB * A_TOTAL;

    // Phase 3a: both-bitmasks for 2 anchors/thread into shared (+ shifted
    // shadow copy for the odd-g aligned path); fg written directly.
    {
        const int a0 = abase + tid * 2;
        if (a0 < A_TOTAL) {
            float fg2[2] = {0.0f, 0.0f};
#pragma unroll
            for (int i = 0; i < 2; ++i) {
                const int a = a0 + i;
                if (a >= A_TOTAL) break;
                int L, row, col;
                anchor_geom(a, L, row, col);
                const int gc = ((L == 0) ? 0 : (L == 1) ? 120 : 180) + col;
                const int gr = ((L == 0) ? 0 : (L == 1) ? 68  : 102) + row;
                const ulonglong2 xe = sx[gc];
                const ulonglong2 ye = sy[gr];
                const unsigned long long box = xe.x & ye.x;
                const unsigned long long ctr = xe.y & ye.y;
                const unsigned long long both = box & ctr;
                const unsigned int lo = (unsigned int)both;
                const unsigned int hi = (unsigned int)(both >> 32);
                const int idx = tid * 2 + i;
                slo[idx] = lo;
                shi[idx] = hi;
                if (idx >= 2) { slo2[idx - 2] = lo; shi2[idx - 2] = hi; }
                // fg = any(box|ctr); "& fg" on ibc redundant (both!=0 => fg)
                fg2[i] = ((box | ctr) != 0ull) ? 1.0f : 0.0f;
            }
            float* pf = out_fg + (size_t)b * A_TOTAL + a0;   // even -> 8B aligned
            if (a0 + 1 < A_TOTAL)
                *reinterpret_cast<float2*>(pf) = make_float2(fg2[0], fg2[1]);
            else
                pf[0] = fg2[0];
        }
    }
    __syncthreads();

    // Phase 3b: flat task loop, 50 g-rows x 128 quads = 6400 tasks, 25/thread.
    float* pbase = out_ibc + (size_t)b * NG * A_TOTAL + abase;

    if (nA == MASK_PER_BLK) {
        // -------- full block: every store is STG.128 --------
#pragma unroll 5
        for (int it = 0; it < 25; ++it) {
            const int task = it * 256 + tid;
            const int g = task >> 7;            // warp-uniform
            const int q = task & 127;
            const int gs = (g < 32) ? g : (g - 32);
            float* prow = pbase + (size_t)g * A_TOTAL;
            if ((g & 1) == 0) {
                const unsigned int* src = (g < 32) ? slo : shi;
                const uint4 w = *reinterpret_cast<const uint4*>(&src[q * 4]);
                // offset q*4: all terms %4==0 -> 16B aligned
                *reinterpret_cast<float4*>(prow + q * 4) =
                    make_float4(bit2f(w.x, gs), bit2f(w.y, gs),
                                bit2f(w.z, gs), bit2f(w.w, gs));
            } else if (q < 127) {
                const unsigned int* src2 = (g < 32) ? slo2 : shi2;
                const uint4 w = *reinterpret_cast<const uint4*>(&src2[q * 4]);
                // anchors q*4+2..q*4+5; odd g => g*A%4==2, +2 -> 16B aligned
                *reinterpret_cast<float4*>(prow + q * 4 + 2) =
                    make_float4(bit2f(w.x, gs), bit2f(w.y, gs),
                                bit2f(w.z, gs), bit2f(w.w, gs));
            } else {
                // edge anchors 0,1 and 510,511 of this odd-g row
                const unsigned int* src = (g < 32) ? slo : shi;
                const uint2 wf = *reinterpret_cast<const uint2*>(&src[0]);
                const uint2 wb = *reinterpret_cast<const uint2*>(&src[510]);
                reinterpret_cast<float2*>(prow)[0] =
                    make_float2(bit2f(wf.x, gs), bit2f(wf.y, gs));
                *reinterpret_cast<float2*>(prow + 510) =
                    make_float2(bit2f(wb.x, gs), bit2f(wb.y, gs));
            }
        }
    } else {
        // -------- tail block (nA=470): generic float2-pair path --------
        const int nquads = (nA + 3) >> 2;
#pragma unroll 5
        for (int it = 0; it < 25; ++it) {
            const int task = it * 256 + tid;
            const int g = task >> 7;
            const int q = task & 127;
            if (q >= nquads) continue;
            const unsigned int* src = (g < 32) ? slo : shi;
            const int gs = (g < 32) ? g : (g - 32);
            const uint4 w = *reinterpret_cast<const uint4*>(&src[q * 4]);
            const float f0 = bit2f(w.x, gs);
            const float f1 = bit2f(w.y, gs);
            const float f2 = bit2f(w.z, gs);
            const float f3 = bit2f(w.w, gs);
            float* p = pbase + (size_t)g * A_TOTAL + q * 4;
            const int rem = nA - q * 4;
            if (rem >= 4) {
                if ((g & 1) == 0) {
                    *reinterpret_cast<float4*>(p) = make_float4(f0, f1, f2, f3);
                } else {
                    reinterpret_cast<float2*>(p)[0] = make_float2(f0, f1);
                    reinterpret_cast<float2*>(p)[1] = make_float2(f2, f3);
                }
            } else {
                if (rem > 0) p[0] = f0;
                if (rem > 1) p[1] = f1;
                if (rem > 2) p[2] = f2;
            }
        }
    }
}

extern "C" void kernel_launch(void* const* d_in, const int* in_sizes, int n_in,
                              void* d_out, int out_size) {
    const float* preds  = (const float*)d_in[0];
    const float* labels = (const float*)d_in[1];
    float* out = (float*)d_out;

    main_kernel<<<MASK_BLOCKS + COPY_BLOCKS, 256>>>(preds, labels, out);
}

// round 14
// speedup vs baseline: 1.0925x; 1.0925x over previous
#include <cuda_runtime.h>
#include <cuda_bf16.h>

// A = 8160 (68x120,s=8) + 2040 (34x60,s=16) + 510 (17x30,s=32) = 10710
// Output: [decoded B*A*16][fg B*A][ibc B*G*A], all f32.
//
// Separable masks: in_box(a,g) = xtest(col) & ytest(row). 50-bit tables per
// column/row; per anchor = 64-bit ANDs. Mask blocks stage per-anchor "both"
// bitmasks in shared (+ a 2-shifted shadow so odd-g rows also use aligned
// 128-bit ld/st), then expand 50 g-rows x 128 quads as a flat task loop.
// All output stores use streaming (.cs) hints: write-once data.

#define A_TOTAL 10710
#define A_L0    8160
#define A_L01   10200
#define NB      32
#define NG      50
#define NCH     16

#define NCOLS   210
#define NROWS   119

#define MASK_PER_BLK 512
#define MASK_ABLKS   ((A_TOTAL + MASK_PER_BLK - 1) / MASK_PER_BLK)  // 21
#define MASK_BLOCKS  (MASK_ABLKS * NB)        // 672
#define TOTF4        (NB * A_TOTAL * 4)       // 1370880
#define COPY_BLOCKS  ((TOTF4 + 511) / 512)    // 2678 (2 float4 per thread)

__device__ __forceinline__ float bit2f(unsigned int word, int g) {
    // ((word >> g) & 1) ? 1.0f : 0.0f  via sign-extend trick (3 ALU ops)
    const unsigned int m = (unsigned int)(((int)(word << (31 - g))) >> 31);
    return __uint_as_float(m & 0x3f800000u);
}

__device__ __forceinline__ void anchor_geom(int a, int& L, int& row, int& col) {
    int i, w;
    if (a < A_L0)       { L = 0; i = a;          w = 120; }
    else if (a < A_L01) { L = 1; i = a - A_L0;   w = 60;  }
    else                { L = 2; i = a - A_L01;  w = 30;  }
    row = i / w;
    col = i - row * w;
}

// global row index 0..118 (monotone in a)
__device__ __forceinline__ int grow_of(int a) {
    if (a < A_L0)   return a / 120;
    if (a < A_L01)  return 68 + (a - A_L0) / 60;
    return 102 + (a - A_L01) / 30;
}

__global__ __launch_bounds__(256)
void main_kernel(const float* __restrict__ preds,
                 const float* __restrict__ labels,
                 float* __restrict__ out) {
    __shared__ float4 sbox[NG];
    __shared__ float4 sctr[3][NG];
    __shared__ ulonglong2 sx[NCOLS];             // .x = box bits, .y = ctr bits
    __shared__ ulonglong2 sy[NROWS];
    __shared__ unsigned int slo[MASK_PER_BLK];   // both bits [0,32)
    __shared__ unsigned int shi[MASK_PER_BLK];   // both bits [32,50)
    __shared__ unsigned int slo2[MASK_PER_BLK];  // slo shifted by 2 (odd-g path)
    __shared__ unsigned int shi2[MASK_PER_BLK];

    const int blk = blockIdx.x;
    const int tid = threadIdx.x;

    if (blk >= MASK_BLOCKS) {
        // ============ copy/decode role: coalesced float4 streaming ==========
        const int cb = blk - MASK_BLOCKS;
        const float4* __restrict__ p4 = reinterpret_cast<const float4*>(preds);
        float4* __restrict__ o4 = reinterpret_cast<float4*>(out);
#pragma unroll
        for (int it = 0; it < 2; ++it) {
            const int j = cb * 512 + it * 256 + tid;
            if (j >= TOTF4) break;
            float4 v = p4[j];
            if ((j & 3) == 0) {                 // channels 0..3 of some anchor
                const int alin = j >> 2;
                const int b = alin / A_TOTAL;
                const int a = alin - b * A_TOTAL;
                int L, row, col;
                anchor_geom(a, L, row, col);
                const float s = (L == 0) ? 8.0f : (L == 1) ? 16.0f : 32.0f;
                float4 r;
                r.x = (v.x + (float)col) * s;
                r.y = (v.y + (float)row) * s;
                r.z = __expf(v.z) * s;
                r.w = __expf(v.w) * s;
                v = r;
            }
            __stcs(&o4[j], v);
        }
        return;
    }

    // ======================= mask role ======================================
    const int b     = blk / MASK_ABLKS;
    const int abase = (blk % MASK_ABLKS) * MASK_PER_BLK;
    const int nA    = min(MASK_PER_BLK, A_TOTAL - abase);
    const int alast = abase + nA - 1;

    const float PINF = __int_as_float(0x7f800000);
    const float NINF = __int_as_float(0xff800000);

    // Phase 1: label bounds into shared
    if (tid < 3 * NG) {
        const int L = tid / NG;
        const int g = tid % NG;
        const float* lb = labels + ((size_t)b * NG + g) * 5;
        const float c  = lb[0];
        const float gx = lb[1];
        const float gy = lb[2];
        const float gw = lb[3];
        const float gh = lb[4];
        const bool valid = (c + gx + gy + gw + gh) > 0.0f;  // invalid rows are exactly 0
        if (L == 0) {
            const float hw = 0.5f * gw, hh = 0.5f * gh;
            sbox[g] = valid ? make_float4(gx - hw, gx + hw, gy - hh, gy + hh)
                            : make_float4(PINF, NINF, PINF, NINF);
        }
        const float r = (L == 0) ? 20.0f : (L == 1) ? 40.0f : 80.0f;  // 2.5*stride
        sctr[L][g] = valid ? make_float4(gx - r, gx + r, gy - r, gy + r)
                           : make_float4(PINF, NINF, PINF, NINF);
    }
    __syncthreads();

    // Phase 2: build ONLY the table entries this block touches (<=193, 1 pass)
    {
        const int Llo = (abase < A_L0) ? 0 : (abase < A_L01) ? 1 : 2;
        const int Lhi = (alast < A_L0) ? 0 : (alast < A_L01) ? 1 : 2;
        const int col_lo = (Llo == 0) ? 0 : (Llo == 1) ? 120 : 180;
        const int col_hi = (Lhi == 0) ? 119 : (Lhi == 1) ? 179 : 209;
        const int row_lo = grow_of(abase);
        const int row_hi = grow_of(alast);
        const int ncols = col_hi - col_lo + 1;
        const int nrows = row_hi - row_lo + 1;     // ncols + nrows <= 193 < 256

        if (tid < ncols) {
            const int gc = col_lo + tid;
            int L, col; float s;
            if (gc < 120)      { L = 0; col = gc;        s = 8.0f;  }
            else if (gc < 180) { L = 1; col = gc - 120;  s = 16.0f; }
            else               { L = 2; col = gc - 180;  s = 32.0f; }
            const float xc = ((float)col + 0.5f) * s;
            unsigned long long bb = 0ull, cc = 0ull;
#pragma unroll
            for (int g = 0; g < NG; ++g) {
                const float4 B = sbox[g];
                const float4 C = sctr[L][g];
                if (fminf(xc - B.x, B.y - xc) > 0.0f) bb |= (1ull << g);
                if (fminf(xc - C.x, C.y - xc) > 0.0f) cc |= (1ull << g);
            }
            sx[gc] = make_ulonglong2(bb, cc);
        } else if (tid < ncols + nrows) {
            const int gr = row_lo + (tid - ncols);
            int L, row; float s;
            if (gr < 68)       { L = 0; row = gr;       s = 8.0f;  }
            else if (gr < 102) { L = 1; row = gr - 68;  s = 16.0f; }
            else               { L = 2; row = gr - 102; s = 32.0f; }
            const float yc = ((float)row + 0.5f) * s;
            unsigned long long bb = 0ull, cc = 0ull;
#pragma unroll
            for (int g = 0; g < NG; ++g) {
                const float4 B = sbox[g];
                const float4 C = sctr[L][g];
                if (fminf(yc - B.z, B.w - yc) > 0.0f) bb |= (1ull << g);
                if (fminf(yc - C.z, C.w - yc) > 0.0f) cc |= (1ull << g);
            }
            sy[gr] = make_ulonglong2(bb, cc);
        }
    }
    __syncthreads();

    float* out_fg  = out + (size_t)NB * A_TOTAL * NCH;
    float* out_ibc = out_fg + (size_t)NB * A_TOTAL;

    // Phase 3a: both-bitmasks for 2 anchors/thread into shared (+ shifted
    // shadow for the odd-g aligned path); fg written directly.
    {
        const int a0 = abase + tid * 2;
        if (a0 < A_TOTAL) {
            float fg2[2] = {0.0f, 0.0f};
#pragma unroll
            for (int i = 0; i < 2; ++i) {
                const int a = a0 + i;
                if (a >= A_TOTAL) break;
                int L, row, col;
                anchor_geom(a, L, row, col);
                const int gc = ((L == 0) ? 0 : (L == 1) ? 120 : 180) + col;
                const int gr = ((L == 0) ? 0 : (L == 1) ? 68  : 102) + row;
                const ulonglong2 xe = sx[gc];
                const ulonglong2 ye = sy[gr];
                const unsigned long long box = xe.x & ye.x;
                const unsigned long long ctr = xe.y & ye.y;
                const unsigned long long both = box & ctr;
                const unsigned int lo = (unsigned int)both;
                const unsigned int hi = (unsigned int)(both >> 32);
                const int idx = tid * 2 + i;
                slo[idx] = lo;
                shi[idx] = hi;
                if (idx >= 2) { slo2[idx - 2] = lo; shi2[idx - 2] = hi; }
                // fg = any(box|ctr); "& fg" on ibc redundant (both!=0 => fg)
                fg2[i] = ((box | ctr) != 0ull) ? 1.0f : 0.0f;
            }
            float* pf = out_fg + (size_t)b * A_TOTAL + a0;   // even -> 8B aligned
            if (a0 + 1 < A_TOTAL) {
                __stcs(reinterpret_cast<float2*>(pf), make_float2(fg2[0], fg2[1]));
            } else {
                __stcs(pf, fg2[0]);
            }
        }
    }
    __syncthreads();

    // Phase 3b: flat task loop, 50 g-rows x 128 quads = 6400 tasks, 25/thread.
    float* pbase = out_ibc + (size_t)b * NG * A_TOTAL + abase;

    if (nA == MASK_PER_BLK) {
        // -------- full block: every store is STG.128 --------
#pragma unroll 5
        for (int it = 0; it < 25; ++it) {
            const int task = it * 256 + tid;
            const int g = task >> 7;            // warp-uniform
            const int q = task & 127;
            const int gs = (g < 32) ? g : (g - 32);
            float* prow = pbase + (size_t)g * A_TOTAL;
            if ((g & 1) == 0) {
                const unsigned int* src = (g < 32) ? slo : shi;
                const uint4 w = *reinterpret_cast<const uint4*>(&src[q * 4]);
                // offset q*4: all terms %4==0 -> 16B aligned
                __stcs(reinterpret_cast<float4*>(prow + q * 4),
                       make_float4(bit2f(w.x, gs), bit2f(w.y, gs),
                                   bit2f(w.z, gs), bit2f(w.w, gs)));
            } else if (q < 127) {
                const unsigned int* src2 = (g < 32) ? slo2 : shi2;
                const uint4 w = *reinterpret_cast<const uint4*>(&src2[q * 4]);
                // anchors q*4+2..q*4+5; odd g => g*A%4==2, +2 -> 16B aligned
                __stcs(reinterpret_cast<float4*>(prow + q * 4 + 2),
                       make_float4(bit2f(w.x, gs), bit2f(w.y, gs),
                                   bit2f(w.z, gs), bit2f(w.w, gs)));
            } else {
                // edge anchors 0,1 and 510,511 of this odd-g row
                const unsigned int* src = (g < 32) ? slo : shi;
                const uint2 wf = *reinterpret_cast<const uint2*>(&src[0]);
                const uint2 wb = *reinterpret_cast<const uint2*>(&src[510]);
                __stcs(reinterpret_cast<float2*>(prow),
                       make_float2(bit2f(wf.x, gs), bit2f(wf.y, gs)));
                __stcs(reinterpret_cast<float2*>(prow + 510),
                       make_float2(bit2f(wb.x, gs), bit2f(wb.y, gs)));
            }
        }
    } else {
        // -------- tail block (nA=470): generic float2-pair path --------
        const int nquads = (nA + 3) >> 2;
#pragma unroll 5
        for (int it = 0; it < 25; ++it) {
            const int task = it * 256 + tid;
            const int g = task >> 7;
            const int q = task & 127;
            if (q >= nquads) continue;
            const unsigned int* src = (g < 32) ? slo : shi;
            const int gs = (g < 32) ? g : (g - 32);
            const uint4 w = *reinterpret_cast<const uint4*>(&src[q * 4]);
            const float f0 = bit2f(w.x, gs);
            const float f1 = bit2f(w.y, gs);
            const float f2 = bit2f(w.z, gs);
            const float f3 = bit2f(w.w, gs);
            float* p = pbase + (size_t)g * A_TOTAL + q * 4;
            const int rem = nA - q * 4;
            if (rem >= 4) {
                if ((g & 1) == 0) {
                    __stcs(reinterpret_cast<float4*>(p),
                           make_float4(f0, f1, f2, f3));
                } else {
                    __stcs(reinterpret_cast<float2*>(p), make_float2(f0, f1));
                    __stcs(reinterpret_cast<float2*>(p) + 1, make_float2(f2, f3));
                }
            } else {
                if (rem > 0) __stcs(&p[0], f0);
                if (rem > 1) __stcs(&p[1], f1);
                if (rem > 2) __stcs(&p[2], f2);
            }
        }
    }
}

extern "C" void kernel_launch(void* const* d_in, const int* in_sizes, int n_in,
                              void* d_out, int out_size) {
    const float* preds  = (const float*)d_in[0];
    const float* labels = (const float*)d_in[1];
    float* out = (float*)d_out;

    main_kernel<<<MASK_BLOCKS + COPY_BLOCKS, 256>>>(preds, labels, out);
}

// round 16
// speedup vs baseline: 1.0986x; 1.0056x over previous
#include <cuda_runtime.h>
#include <cuda_bf16.h>

// A = 8160 (68x120,s=8) + 2040 (34x60,s=16) + 510 (17x30,s=32) = 10710
// Output: [decoded B*A*16][fg B*A][ibc B*G*A], all f32.
//
// Separable masks: in_box(a,g) = xtest(col) & ytest(row). 50-bit tables per
// column/row; per anchor = 64-bit ANDs. Mask blocks stage per-anchor "both"
// bitmasks in shared (+ a 2-shifted shadow so odd-g rows also use aligned
// 128-bit ld/st). Expansion: thread owns one quad and one g-PARITY
// (tid>>7), so its mask words are loaded once and every g/shift in the
// unrolled loop is a compile-time constant. All output stores stream (.cs).

#define A_TOTAL 10710
#define A_L0    8160
#define A_L01   10200
#define NB      32
#define NG      50
#define NCH     16

#define NCOLS   210
#define NROWS   119

#define MASK_PER_BLK 512
#define MASK_ABLKS   ((A_TOTAL + MASK_PER_BLK - 1) / MASK_PER_BLK)  // 21
#define MASK_BLOCKS  (MASK_ABLKS * NB)        // 672
#define TOTF4        (NB * A_TOTAL * 4)       // 1370880
#define COPY_BLOCKS  ((TOTF4 + 511) / 512)    // 2678 (2 float4 per thread)

__device__ __forceinline__ float bit2f(unsigned int word, int g) {
    // ((word >> g) & 1) ? 1.0f : 0.0f  via sign-extend trick (3 ALU ops)
    const unsigned int m = (unsigned int)(((int)(word << (31 - g))) >> 31);
    return __uint_as_float(m & 0x3f800000u);
}

__device__ __forceinline__ void anchor_geom(int a, int& L, int& row, int& col) {
    int i, w;
    if (a < A_L0)       { L = 0; i = a;          w = 120; }
    else if (a < A_L01) { L = 1; i = a - A_L0;   w = 60;  }
    else                { L = 2; i = a - A_L01;  w = 30;  }
    row = i / w;
    col = i - row * w;
}

// global row index 0..118 (monotone in a)
__device__ __forceinline__ int grow_of(int a) {
    if (a < A_L0)   return a / 120;
    if (a < A_L01)  return 68 + (a - A_L0) / 60;
    return 102 + (a - A_L01) / 30;
}

__global__ __launch_bounds__(256)
void main_kernel(const float* __restrict__ preds,
                 const float* __restrict__ labels,
                 float* __restrict__ out) {
    __shared__ float4 sbox[NG];
    __shared__ float4 sctr[3][NG];
    __shared__ ulonglong2 sx[NCOLS];             // .x = box bits, .y = ctr bits
    __shared__ ulonglong2 sy[NROWS];
    __shared__ unsigned int slo[MASK_PER_BLK];   // both bits [0,32)
    __shared__ unsigned int shi[MASK_PER_BLK];   // both bits [32,50)
    __shared__ unsigned int slo2[MASK_PER_BLK];  // slo shifted by 2 (odd-g path)
    __shared__ unsigned int shi2[MASK_PER_BLK];

    const int blk = blockIdx.x;
    const int tid = threadIdx.x;

    if (blk >= MASK_BLOCKS) {
        // ============ copy/decode role: coalesced float4 streaming ==========
        const int cb = blk - MASK_BLOCKS;
        const float4* __restrict__ p4 = reinterpret_cast<const float4*>(preds);
        float4* __restrict__ o4 = reinterpret_cast<float4*>(out);
#pragma unroll
        for (int it = 0; it < 2; ++it) {
            const int j = cb * 512 + it * 256 + tid;
            if (j >= TOTF4) break;
            float4 v = p4[j];
            if ((j & 3) == 0) {                 // channels 0..3 of some anchor
                const int alin = j >> 2;
                const int b = alin / A_TOTAL;
                const int a = alin - b * A_TOTAL;
                int L, row, col;
                anchor_geom(a, L, row, col);
                const float s = (L == 0) ? 8.0f : (L == 1) ? 16.0f : 32.0f;
                float4 r;
                r.x = (v.x + (float)col) * s;
                r.y = (v.y + (float)row) * s;
                r.z = __expf(v.z) * s;
                r.w = __expf(v.w) * s;
                v = r;
            }
            __stcs(&o4[j], v);
        }
        return;
    }

    // ======================= mask role ======================================
    const int b     = blk / MASK_ABLKS;
    const int abase = (blk % MASK_ABLKS) * MASK_PER_BLK;
    const int nA    = min(MASK_PER_BLK, A_TOTAL - abase);
    const int alast = abase + nA - 1;

    const float PINF = __int_as_float(0x7f800000);
    const float NINF = __int_as_float(0xff800000);

    // Phase 1: label bounds into shared
    if (tid < 3 * NG) {
        const int L = tid / NG;
        const int g = tid % NG;
        const float* lb = labels + ((size_t)b * NG + g) * 5;
        const float c  = lb[0];
        const float gx = lb[1];
        const float gy = lb[2];
        const float gw = lb[3];
        const float gh = lb[4];
        const bool valid = (c + gx + gy + gw + gh) > 0.0f;  // invalid rows are exactly 0
        if (L == 0) {
            const float hw = 0.5f * gw, hh = 0.5f * gh;
            sbox[g] = valid ? make_float4(gx - hw, gx + hw, gy - hh, gy + hh)
                            : make_float4(PINF, NINF, PINF, NINF);
        }
        const float r = (L == 0) ? 20.0f : (L == 1) ? 40.0f : 80.0f;  // 2.5*stride
        sctr[L][g] = valid ? make_float4(gx - r, gx + r, gy - r, gy + r)
                           : make_float4(PINF, NINF, PINF, NINF);
    }
    __syncthreads();

    // Phase 2: build ONLY the table entries this block touches (<=193, 1 pass)
    {
        const int Llo = (abase < A_L0) ? 0 : (abase < A_L01) ? 1 : 2;
        const int Lhi = (alast < A_L0) ? 0 : (alast < A_L01) ? 1 : 2;
        const int col_lo = (Llo == 0) ? 0 : (Llo == 1) ? 120 : 180;
        const int col_hi = (Lhi == 0) ? 119 : (Lhi == 1) ? 179 : 209;
        const int row_lo = grow_of(abase);
        const int row_hi = grow_of(alast);
        const int ncols = col_hi - col_lo + 1;
        const int nrows = row_hi - row_lo + 1;     // ncols + nrows <= 193 < 256

        if (tid < ncols) {
            const int gc = col_lo + tid;
            int L, col; float s;
            if (gc < 120)      { L = 0; col = gc;        s = 8.0f;  }
            else if (gc < 180) { L = 1; col = gc - 120;  s = 16.0f; }
            else               { L = 2; col = gc - 180;  s = 32.0f; }
            const float xc = ((float)col + 0.5f) * s;
            unsigned long long bb = 0ull, cc = 0ull;
#pragma unroll
            for (int g = 0; g < NG; ++g) {
                const float4 B = sbox[g];
                const float4 C = sctr[L][g];
                if (fminf(xc - B.x, B.y - xc) > 0.0f) bb |= (1ull << g);
                if (fminf(xc - C.x, C.y - xc) > 0.0f) cc |= (1ull << g);
            }
            sx[gc] = make_ulonglong2(bb, cc);
        } else if (tid < ncols + nrows) {
            const int gr = row_lo + (tid - ncols);
            int L, row; float s;
            if (gr < 68)       { L = 0; row = gr;       s = 8.0f;  }
            else if (gr < 102) { L = 1; row = gr - 68;  s = 16.0f; }
            else               { L = 2; row = gr - 102; s = 32.0f; }
            const float yc = ((float)row + 0.5f) * s;
            unsigned long long bb = 0ull, cc = 0ull;
#pragma unroll
            for (int g = 0; g < NG; ++g) {
                const float4 B = sbox[g];
                const float4 C = sctr[L][g];
                if (fminf(yc - B.z, B.w - yc) > 0.0f) bb |= (1ull << g);
                if (fminf(yc - C.z, C.w - yc) > 0.0f) cc |= (1ull << g);
            }
            sy[gr] = make_ulonglong2(bb, cc);
        }
    }
    __syncthreads();

    float* out_fg  = out + (size_t)NB * A_TOTAL * NCH;
    float* out_ibc = out_fg + (size_t)NB * A_TOTAL;

    // Phase 3a: both-bitmasks for 2 anchors/thread into shared (+ shifted
    // shadow for the odd-g aligned path); fg written directly.
    {
        const int a0 = abase + tid * 2;
        if (a0 < A_TOTAL) {
            float fg2[2] = {0.0f, 0.0f};
#pragma unroll
            for (int i = 0; i < 2; ++i) {
                const int a = a0 + i;
                if (a >= A_TOTAL) break;
                int L, row, col;
                anchor_geom(a, L, row, col);
                const int gc = ((L == 0) ? 0 : (L == 1) ? 120 : 180) + col;
                const int gr = ((L == 0) ? 0 : (L == 1) ? 68  : 102) + row;
                const ulonglong2 xe = sx[gc];
                const ulonglong2 ye = sy[gr];
                const unsigned long long box = xe.x & ye.x;
                const unsigned long long ctr = xe.y & ye.y;
                const unsigned long long both = box & ctr;
                const unsigned int lo = (unsigned int)both;
                const unsigned int hi = (unsigned int)(both >> 32);
                const int idx = tid * 2 + i;
                slo[idx] = lo;
                shi[idx] = hi;
                if (idx >= 2) { slo2[idx - 2] = lo; shi2[idx - 2] = hi; }
                // fg = any(box|ctr); "& fg" on ibc redundant (both!=0 => fg)
                fg2[i] = ((box | ctr) != 0ull) ? 1.0f : 0.0f;
            }
            float* pf = out_fg + (size_t)b * A_TOTAL + a0;   // even -> 8B aligned
            if (a0 + 1 < A_TOTAL) {
                __stcs(reinterpret_cast<float2*>(pf), make_float2(fg2[0], fg2[1]));
            } else {
                __stcs(pf, fg2[0]);
            }
        }
    }
    __syncthreads();

    // Phase 3b: parity-split quad-owner expansion.
    // q = tid&127 owns anchors [q*4, q*4+4); h = tid>>7 fixes the g-parity
    // this thread writes (g = 2*it + h). Mask words are loaded ONCE; every
    // g, shift amount and lo/hi choice below is a compile-time constant.
    // Warp store pattern: 32 consecutive q on one g-row (identical to R10).
    float* pbase = out_ibc + (size_t)b * NG * A_TOTAL + abase;

    if (nA == MASK_PER_BLK) {
        const int q = tid & 127;
        const int h = tid >> 7;
        if (h == 0) {
            // even g rows: g = 0,2,...,48 ; offsets q*4 are 16B aligned
            const uint4 wlo = *reinterpret_cast<const uint4*>(&slo[q * 4]);
            const uint4 whi = *reinterpret_cast<const uint4*>(&shi[q * 4]);
            float* p = pbase + q * 4;
#pragma unroll
            for (int it = 0; it < 25; ++it) {
                const int g = 2 * it;                       // compile-time
                const uint4 w = (g < 32) ? wlo : whi;
                const int gs = (g < 32) ? g : g - 32;
                __stcs(reinterpret_cast<float4*>(p),
                       make_float4(bit2f(w.x, gs), bit2f(w.y, gs),
                                   bit2f(w.z, gs), bit2f(w.w, gs)));
                p += 2 * A_TOTAL;
            }
        } else if (q < 127) {
            // odd g rows: g = 1,3,...,49 ; anchors q*4+2..q*4+5 via shadow,
            // offset q*4+2: odd g => g*A%4==2, +2 -> 16B aligned
            const uint4 wlo = *reinterpret_cast<const uint4*>(&slo2[q * 4]);
            const uint4 whi = *reinterpret_cast<const uint4*>(&shi2[q * 4]);
            float* p = pbase + (size_t)A_TOTAL + q * 4 + 2;
#pragma unroll
            for (int it = 0; it < 25; ++it) {
                const int g = 2 * it + 1;                   // compile-time
                const uint4 w = (g < 32) ? wlo : whi;
                const int gs = (g < 32) ? g : g - 32;
                __stcs(reinterpret_cast<float4*>(p),
                       make_float4(bit2f(w.x, gs), bit2f(w.y, gs),
                                   bit2f(w.z, gs), bit2f(w.w, gs)));
                p += 2 * A_TOTAL;
            }
        } else {
            // h==1, q==127: edge anchors {0,1} and {510,511} of each odd row
            const uint2 wlo_f = *reinterpret_cast<const uint2*>(&slo[0]);
            const uint2 whi_f = *reinterpret_cast<const uint2*>(&shi[0]);
            const uint2 wlo_b = *reinterpret_cast<const uint2*>(&slo[510]);
            const uint2 whi_b = *reinterpret_cast<const uint2*>(&shi[510]);
            float* p = pbase + (size_t)A_TOTAL;
#pragma unroll
            for (int it = 0; it < 25; ++it) {
                const int g = 2 * it + 1;                   // compile-time
                const uint2 wf = (g < 32) ? wlo_f : whi_f;
                const uint2 wb = (g < 32) ? wlo_b : whi_b;
                const int gs = (g < 32) ? g : g - 32;
                __stcs(reinterpret_cast<float2*>(p),
                       make_float2(bit2f(wf.x, gs), bit2f(wf.y, gs)));
                __stcs(reinterpret_cast<float2*>(p + 510),
                       make_float2(bit2f(wb.x, gs), bit2f(wb.y, gs)));
                p += 2 * A_TOTAL;
            }
        }
    } else {
        // -------- tail block (nA=470): generic task-loop path --------
        const int nquads = (nA + 3) >> 2;
#pragma unroll 5
        for (int it = 0; it < 25; ++it) {
            const int task = it * 256 + tid;
            const int g = task >> 7;
            const int q = task & 127;
            if (q >= nquads) continue;
            const unsigned int* src = (g < 32) ? slo : shi;
            const int gs = (g < 32) ? g : (g - 32);
            const uint4 w = *reinterpret_cast<const uint4*>(&src[q * 4]);
            const float f0 = bit2f(w.x, gs);
            const float f1 = bit2f(w.y, gs);
            const float f2 = bit2f(w.z, gs);
            const float f3 = bit2f(w.w, gs);
            float* p = pbase + (size_t)g * A_TOTAL + q * 4;
            const int rem = nA - q * 4;
            if (rem >= 4) {
                if ((g & 1) == 0) {
                    __stcs(reinterpret_cast<float4*>(p),
                           make_float4(f0, f1, f2, f3));
                } else {
                    __stcs(reinterpret_cast<float2*>(p), make_float2(f0, f1));
                    __stcs(reinterpret_cast<float2*>(p) + 1, make_float2(f2, f3));
                }
            } else {
                if (rem > 0) __stcs(&p[0], f0);
                if (rem > 1) __stcs(&p[1], f1);
                if (rem > 2) __stcs(&p[2], f2);
            }
        }
    }
}

extern "C" void kernel_launch(void* const* d_in, const int* in_sizes, int n_in,
                              void* d_out, int out_size) {
    const float* preds  = (const float*)d_in[0];
    const float* labels = (const float*)d_in[1];
    float* out = (float*)d_out;

    main_kernel<<<MASK_BLOCKS + COPY_BLOCKS, 256>>>(preds, labels, out);
}